// round 4
// baseline (speedup 1.0000x reference)
#include <cuda_runtime.h>
#include <math.h>

#define NN 50000
#define EE 500000
#define DD 64
#define GG 50
#define NPG 1000   // nodes per graph
#define CSRB 196   // blocks in fused CSR kernel (all-resident => safe grid barrier)

// ---------------- scratch (static device globals; no runtime alloc) ----------------
__device__ __align__(16) float g_hr  [NN*DD];   // raw (pre-pairnorm) node features
__device__ __align__(16) float g_a   [NN*DD];
__device__ __align__(16) float g_b   [NN*DD];
__device__ int   g_cnt[NN];
__device__ int   g_rowptr[NN+1];
__device__ __align__(8) int2 g_csr[EE];         // {src, float_as_int(dist)}
__device__ __align__(16) float g_stats[DD+1];   // colsum[64], sumsq (accumulated by upd)
__device__ __align__(16) float g_norm [DD+1];   // mu[64], inv  (consumed lazily)
__device__ int   g_bsum[256];
__device__ int   g_barcnt = 0;
__device__ int   g_bargen = 0;
__device__ int   g_done   = 0;

// ---- software grid barrier (valid: all CSRB blocks resident) ----
__device__ __forceinline__ void grid_barrier() {
    __syncthreads();
    if (threadIdx.x == 0) {
        __threadfence();
        int gen = *(volatile int*)&g_bargen;
        if (atomicAdd(&g_barcnt, 1) == (int)gridDim.x - 1) {
            atomicExch(&g_barcnt, 0);
            __threadfence();
            atomicAdd(&g_bargen, 1);
        } else {
            while (*(volatile int*)&g_bargen == gen) { }
        }
        __threadfence();
    }
    __syncthreads();
}

// ---------------- fused: CSR build + input embedding + norm/stats init ----------------
__global__ void __launch_bounds__(256) k_csr_build(const int*   __restrict__ ei,
                                                   const float* __restrict__ pos,
                                                   const float* __restrict__ hin,
                                                   const float* __restrict__ Wemb,
                                                   const float* __restrict__ bemb) {
    __shared__ int s[256];
    int tid = threadIdx.x;
    int bid = blockIdx.x;
    int gt  = bid * 256 + tid;

    // init identity norm + zero stats (block 0)
    if (gt < 64)  { g_norm[gt] = 0.f; g_stats[gt] = 0.f; }
    if (gt == 64) { g_norm[64] = 1.f; g_stats[64] = 0.f; g_done = 0; }

    // P0: zero counts
    if (gt < NN) g_cnt[gt] = 0;
    grid_barrier();

    // P1: count in-degree
    for (int e = gt; e < EE; e += CSRB * 256)
        atomicAdd(&g_cnt[ei[EE + e]], 1);
    grid_barrier();

    // P2: per-block scan
    {
        int c = (gt < NN) ? g_cnt[gt] : 0;
        s[tid] = c;
        __syncthreads();
        #pragma unroll
        for (int off = 1; off < 256; off <<= 1) {
            int t = 0;
            if (tid >= off) t = s[tid - off];
            __syncthreads();
            s[tid] += t;
            __syncthreads();
        }
        if (gt < NN) g_rowptr[gt] = s[tid] - c;
        if (tid == 255) g_bsum[bid] = s[255];
    }
    grid_barrier();

    // P3: scan block sums
    if (bid == 0) {
        int c = (tid < CSRB) ? g_bsum[tid] : 0;
        s[tid] = c;
        __syncthreads();
        #pragma unroll
        for (int off = 1; off < 256; off <<= 1) {
            int t = 0;
            if (tid >= off) t = s[tid - off];
            __syncthreads();
            s[tid] += t;
            __syncthreads();
        }
        if (tid < CSRB) g_bsum[tid] = s[tid] - c;
    }
    grid_barrier();

    // P4: globalize rowptr + cursors
    if (gt < NN) {
        int r = g_rowptr[gt] + g_bsum[bid];
        g_rowptr[gt] = r;
        g_cnt[gt] = r;
    }
    if (gt == 0) g_rowptr[NN] = EE;
    grid_barrier();

    // P5: fill CSR
    for (int e = gt; e < EE; e += CSRB * 256) {
        int sn = ei[e];
        int d  = ei[EE + e];
        int p  = atomicAdd(&g_cnt[d], 1);
        float dx = pos[2*d]   - pos[2*sn];
        float dy = pos[2*d+1] - pos[2*sn+1];
        g_csr[p] = make_int2(sn, __float_as_int(sqrtf(dx*dx + dy*dy)));
    }

    // P6: embedding (independent)
    int w0   = gt >> 5;
    int lane = tid & 31;
    int nw   = (CSRB * 256) >> 5;
    int c0   = lane * 2;
    for (int w = w0; w < NN; w += nw) {
        float v0 = hin[w*5+0], v1 = hin[w*5+1], v2 = hin[w*5+2],
              v3 = hin[w*5+3], v4 = hin[w*5+4];
        #pragma unroll
        for (int j = 0; j < 2; j++) {
            int c = c0 + j;
            float acc = bemb[c] + v0*Wemb[c] + v1*Wemb[64+c] + v2*Wemb[128+c]
                                + v3*Wemb[192+c] + v4*Wemb[256+c];
            g_hr[w*64+c] = fmaxf(acc, 0.f);
        }
    }
}

// ---------------- GEMM: [a|b] = pairnorm(hr) @ Wm_remap  (full-stage, 1 sync) ----------------
__global__ void __launch_bounds__(256) k_gemm_ab(const float* __restrict__ Wm) {
    extern __shared__ float sm[];
    float* sXT = sm;                 // [64][129]
    float* sW  = sm + 64*129;        // [64][128]
    int tid  = threadIdx.x;
    int base = blockIdx.x * 128;
    float inv = g_norm[64];

    // stage X^T with pairnorm applied: 128 nodes x 64 k
    #pragma unroll
    for (int it = 0; it < 8; it++) {
        int idx = tid + 256*it;      // over 2048 float4
        int nl  = idx >> 4;          // 0..127
        int kq  = idx & 15;          // float4 idx
        int n   = base + nl;
        float4 v = make_float4(0.f,0.f,0.f,0.f);
        if (n < NN) v = *(const float4*)&g_hr[n*64 + kq*4];
        float4 mu = *(const float4*)&g_norm[kq*4];
        v.x = (v.x - mu.x)*inv; v.y = (v.y - mu.y)*inv;
        v.z = (v.z - mu.z)*inv; v.w = (v.w - mu.w)*inv;
        sXT[(kq*4+0)*129 + nl] = v.x;
        sXT[(kq*4+1)*129 + nl] = v.y;
        sXT[(kq*4+2)*129 + nl] = v.z;
        sXT[(kq*4+3)*129 + nl] = v.w;
    }
    // stage W remap: col c<64 -> Wm[k][c]; c>=64 -> Wm[64+k][c-64]
    #pragma unroll
    for (int it = 0; it < 32; it++) {
        int idx = tid + 256*it;      // over 8192 floats
        int c   = idx & 127;
        int kk  = idx >> 7;          // 0..63
        int row = (c < 64) ? kk : (64 + kk);
        sW[kk*128 + c] = Wm[row*64 + (c & 63)];
    }
    __syncthreads();

    int ng = tid & 15;
    int cg = tid >> 4;               // 0..15 -> cols cg*8..+7 of 128
    float acc[8][8];
    #pragma unroll
    for (int i = 0; i < 8; i++)
        #pragma unroll
        for (int j = 0; j < 8; j++) acc[i][j] = 0.f;

    #pragma unroll
    for (int kk = 0; kk < 64; kk++) {
        float xv[8];
        #pragma unroll
        for (int i = 0; i < 8; i++) xv[i] = sXT[kk*129 + ng + 16*i];
        float4 wA = *(const float4*)&sW[kk*128 + cg*8];
        float4 wB = *(const float4*)&sW[kk*128 + cg*8 + 4];
        float wv[8] = {wA.x,wA.y,wA.z,wA.w,wB.x,wB.y,wB.z,wB.w};
        #pragma unroll
        for (int i = 0; i < 8; i++)
            #pragma unroll
            for (int j = 0; j < 8; j++)
                acc[i][j] = fmaf(xv[i], wv[j], acc[i][j]);
    }

    float* Out = (cg < 8) ? g_a : g_b;
    int c0     = (cg < 8) ? cg*8 : cg*8 - 64;
    #pragma unroll
    for (int i = 0; i < 8; i++) {
        int n = base + ng + 16*i;
        if (n < NN) {
            *(float4*)&Out[n*64 + c0]     = make_float4(acc[i][0],acc[i][1],acc[i][2],acc[i][3]);
            *(float4*)&Out[n*64 + c0 + 4] = make_float4(acc[i][4],acc[i][5],acc[i][6],acc[i][7]);
        }
    }
}

// ---------------- fused: edge gather + update GEMM + stats + last-block norm finalize ----------------
__global__ void __launch_bounds__(256) k_upd(const float* __restrict__ Wm,
                                             const float* __restrict__ bm,
                                             const float* __restrict__ Wu,
                                             const float* __restrict__ bu) {
    extern __shared__ float sm[];
    float* sXT = sm;                 // [64][129]  pairnorm(h)^T
    float* sAG = sm + 64*129;        // [64][129]  aggr^T
    float* sW  = sm + 2*64*129;      // [128][64]
    int tid  = threadIdx.x;
    int base = blockIdx.x * 128;
    int w    = tid >> 5;
    int lane = tid & 31;

    // ---- Phase A: gather into sAG (8 warps x 16 nodes), MLP=8 batched ----
    {
        int c0 = lane*2;
        float wdx = Wm[128*64 + c0], wdy = Wm[128*64 + c0 + 1];
        float bmx = bm[c0], bmy = bm[c0+1];
        #pragma unroll 1
        for (int t = 0; t < 16; t++) {
            int nl = w*16 + t;
            int n  = base + nl;
            if (n >= NN) break;
            float2 av = *(const float2*)&g_a[n*64 + c0];
            float pax = av.x + bmx;
            float pay = av.y + bmy;
            float ax = 0.f, ay = 0.f;
            int st = g_rowptr[n], en = g_rowptr[n+1];
            for (int eb = st; eb < en; eb += 8) {
                int mm = en - eb; if (mm > 8) mm = 8;
                int2 ed = make_int2(0, 0);
                if (lane < mm) ed = g_csr[eb + lane];
                float2 bv[8];
                float  dv[8];
                #pragma unroll
                for (int j = 0; j < 8; j++) {
                    int sidx = __shfl_sync(0xffffffffu, ed.x, j);
                    int dbit = __shfl_sync(0xffffffffu, ed.y, j);
                    dv[j] = __int_as_float(dbit);
                    if (j < mm) bv[j] = *(const float2*)&g_b[sidx*64 + c0];
                }
                #pragma unroll
                for (int j = 0; j < 8; j++) {
                    if (j < mm) {
                        ax += fmaxf(pax + bv[j].x + dv[j]*wdx, 0.f);
                        ay += fmaxf(pay + bv[j].y + dv[j]*wdy, 0.f);
                    }
                }
            }
            sAG[(c0  )*129 + nl] = ax;
            sAG[(c0+1)*129 + nl] = ay;
        }
    }

    // ---- stage pairnorm(h)^T and Wu ----
    float inv = g_norm[64];
    #pragma unroll
    for (int it = 0; it < 8; it++) {
        int idx = tid + 256*it;      // over 2048 float4
        int nl  = idx >> 4;
        int kq  = idx & 15;
        int n   = base + nl;
        float4 v = make_float4(0.f,0.f,0.f,0.f);
        if (n < NN) v = *(const float4*)&g_hr[n*64 + kq*4];
        float4 mu = *(const float4*)&g_norm[kq*4];
        v.x = (v.x - mu.x)*inv; v.y = (v.y - mu.y)*inv;
        v.z = (v.z - mu.z)*inv; v.w = (v.w - mu.w)*inv;
        sXT[(kq*4+0)*129 + nl] = v.x;
        sXT[(kq*4+1)*129 + nl] = v.y;
        sXT[(kq*4+2)*129 + nl] = v.z;
        sXT[(kq*4+3)*129 + nl] = v.w;
    }
    #pragma unroll
    for (int it = 0; it < 32; it++) {
        int idx = tid + 256*it;      // 8192 floats, straight copy
        sW[idx] = Wu[idx];
    }
    __syncthreads();

    // ---- Phase B: GEMM  acc[4][8]: nodes ng+32i, cols cg*8..+7 (cg = warp id) ----
    int ng = lane;                   // 0..31 (tid&31)
    int cg = w;                      // 0..7
    float acc[4][8];
    #pragma unroll
    for (int i = 0; i < 4; i++)
        #pragma unroll
        for (int j = 0; j < 8; j++) acc[i][j] = 0.f;

    #pragma unroll
    for (int kk = 0; kk < 64; kk++) {
        float xv[4];
        #pragma unroll
        for (int i = 0; i < 4; i++) xv[i] = sXT[kk*129 + ng + 32*i];
        float4 wA = *(const float4*)&sW[kk*64 + cg*8];
        float4 wB = *(const float4*)&sW[kk*64 + cg*8 + 4];
        float wv[8] = {wA.x,wA.y,wA.z,wA.w,wB.x,wB.y,wB.z,wB.w};
        #pragma unroll
        for (int i = 0; i < 4; i++)
            #pragma unroll
            for (int j = 0; j < 8; j++)
                acc[i][j] = fmaf(xv[i], wv[j], acc[i][j]);
    }
    #pragma unroll
    for (int kk = 0; kk < 64; kk++) {
        float xv[4];
        #pragma unroll
        for (int i = 0; i < 4; i++) xv[i] = sAG[kk*129 + ng + 32*i];
        float4 wA = *(const float4*)&sW[(64+kk)*64 + cg*8];
        float4 wB = *(const float4*)&sW[(64+kk)*64 + cg*8 + 4];
        float wv[8] = {wA.x,wA.y,wA.z,wA.w,wB.x,wB.y,wB.z,wB.w};
        #pragma unroll
        for (int i = 0; i < 4; i++)
            #pragma unroll
            for (int j = 0; j < 8; j++)
                acc[i][j] = fmaf(xv[i], wv[j], acc[i][j]);
    }

    // ---- epilogue: bias+relu, store raw h, accumulate pairnorm stats ----
    float4 bA = *(const float4*)&bu[cg*8];
    float4 bB = *(const float4*)&bu[cg*8 + 4];
    float bvv[8] = {bA.x,bA.y,bA.z,bA.w,bB.x,bB.y,bB.z,bB.w};
    float ls[8] = {0,0,0,0,0,0,0,0};
    float lss = 0.f;
    #pragma unroll
    for (int i = 0; i < 4; i++) {
        int n = base + ng + 32*i;
        if (n < NN) {
            float o[8];
            #pragma unroll
            for (int j = 0; j < 8; j++) {
                o[j] = fmaxf(acc[i][j] + bvv[j], 0.f);
                ls[j] += o[j];
                lss   += o[j]*o[j];
            }
            *(float4*)&g_hr[n*64 + cg*8]     = make_float4(o[0],o[1],o[2],o[3]);
            *(float4*)&g_hr[n*64 + cg*8 + 4] = make_float4(o[4],o[5],o[6],o[7]);
        }
    }
    // warp reduce (all lanes share cg)
    #pragma unroll
    for (int off = 16; off > 0; off >>= 1) {
        #pragma unroll
        for (int j = 0; j < 8; j++)
            ls[j] += __shfl_down_sync(0xffffffffu, ls[j], off);
        lss += __shfl_down_sync(0xffffffffu, lss, off);
    }
    if (lane == 0) {
        #pragma unroll
        for (int j = 0; j < 8; j++) atomicAdd(&g_stats[cg*8 + j], ls[j]);
        atomicAdd(&g_stats[64], lss);
    }

    // ---- last block finalizes g_norm for the next consumer, re-arms stats ----
    __shared__ int isLast;
    __threadfence();
    __syncthreads();
    if (tid == 0)
        isLast = (atomicAdd(&g_done, 1) == (int)gridDim.x - 1) ? 1 : 0;
    __syncthreads();
    if (isLast) {
        __shared__ float spart[2];
        if (tid < 64) {
            float mu = g_stats[tid] * (1.0f/NN);
            g_norm[tid] = mu;
            float m2 = mu*mu;
            #pragma unroll
            for (int off = 16; off > 0; off >>= 1)
                m2 += __shfl_down_sync(0xffffffffu, m2, off);
            if ((tid & 31) == 0) spart[tid >> 5] = m2;
        }
        __syncthreads();
        if (tid == 0) {
            float musq = spart[0] + spart[1];
            g_norm[64] = 1.0f / sqrtf(1e-5f + g_stats[64]*(1.0f/NN) - musq);
            g_done = 0;
        }
        __syncthreads();
        if (tid < 65) g_stats[tid] = 0.f;   // re-arm for next layer
    }
}

// ---------------- per-graph max pool (on raw h + lazy norm) + tiny MLP ----------------
__global__ void k_pool(const float* __restrict__ W1, const float* __restrict__ b1,
                       const float* __restrict__ W2, const float* __restrict__ b2,
                       float* __restrict__ out) {
    __shared__ float red[4][64];
    __shared__ float hg[64];
    __shared__ float z[64];
    int g   = blockIdx.x;
    int tid = threadIdx.x;
    int c     = tid & 63;
    int chunk = tid >> 6;
    float m = -3.4e38f;
    int nbeg = g*NPG + chunk*(NPG/4);
    for (int i = 0; i < NPG/4; i++)
        m = fmaxf(m, g_hr[(nbeg + i)*64 + c]);
    red[chunk][c] = m;
    __syncthreads();
    if (tid < 64) {
        float mr = fmaxf(fmaxf(red[0][tid], red[1][tid]),
                         fmaxf(red[2][tid], red[3][tid]));
        // pairnorm is monotone per column: max(norm(v)) = norm(max(v))
        hg[tid] = (mr - g_norm[tid]) * g_norm[64];
    }
    __syncthreads();
    if (tid < 64) {
        float acc = b1[tid];
        for (int k = 0; k < 64; k++) acc = fmaf(hg[k], W1[k*64 + tid], acc);
        z[tid] = fmaxf(acc, 0.f);
    }
    __syncthreads();
    if (tid < 2) {
        float acc = b2[tid];
        for (int k = 0; k < 64; k++) acc = fmaf(z[k], W2[k*2 + tid], acc);
        out[g*2 + tid] = acc;
    }
}

// ---------------- launch ----------------
extern "C" void kernel_launch(void* const* d_in, const int* in_sizes, int n_in,
                              void* d_out, int out_size) {
    const float* h_in = (const float*)d_in[0];
    const float* pos  = (const float*)d_in[1];
    const int*   ei   = (const int*)  d_in[2];
    // d_in[3] = batch — structure fixed (contiguous 1000-node graphs), unused
    const float* Wemb = (const float*)d_in[4];
    const float* bemb = (const float*)d_in[5];
    const float* msgW = (const float*)d_in[6];
    const float* msgb = (const float*)d_in[7];
    const float* updW = (const float*)d_in[8];
    const float* updb = (const float*)d_in[9];
    const float* W1   = (const float*)d_in[10];
    const float* b1   = (const float*)d_in[11];
    const float* W2   = (const float*)d_in[12];
    const float* b2   = (const float*)d_in[13];
    float* out = (float*)d_out;

    const int AB_SMEM  = (64*129 + 64*128) * 4;          // 65,792 B
    const int UPD_SMEM = (2*64*129 + 128*64) * 4;        // 98,816 B
    static int attr_done = 0;
    if (!attr_done) {
        cudaFuncSetAttribute(k_gemm_ab, cudaFuncAttributeMaxDynamicSharedMemorySize, AB_SMEM);
        cudaFuncSetAttribute(k_upd,     cudaFuncAttributeMaxDynamicSharedMemorySize, UPD_SMEM);
        attr_done = 1;
    }

    k_csr_build<<<CSRB, 256>>>(ei, pos, h_in, Wemb, bemb);

    for (int l = 0; l < 2; l++) {
        const float* Wm = msgW + l*129*64;
        const float* bm = msgb + l*64;
        const float* Wu = updW + l*128*64;
        const float* bu = updb + l*64;
        k_gemm_ab<<<391, 256, AB_SMEM>>>(Wm);
        k_upd    <<<391, 256, UPD_SMEM>>>(Wm, bm, Wu, bu);
    }

    k_pool<<<50, 256>>>(W1, b1, W2, b2, out);
}

// round 5
// speedup vs baseline: 1.2808x; 1.2808x over previous
#include <cuda_runtime.h>
#include <math.h>

#define NN 50000
#define EE 500000
#define DD 64
#define GG 50
#define NPG 1000   // nodes per graph
#define CSRB 196   // blocks in fused CSR kernel (all-resident => safe grid barrier)

// ---------------- scratch (static device globals; no runtime alloc) ----------------
__device__ __align__(16) float g_hr  [NN*DD];   // raw (pre-pairnorm) node features
__device__ __align__(16) float g_a   [NN*DD];
__device__ __align__(16) float g_b   [NN*DD];
__device__ __align__(16) float g_aggr[NN*DD];
__device__ int   g_cnt[NN];
__device__ int   g_rowptr[NN+1];
__device__ __align__(8) int2 g_csr[EE];         // {src, float_as_int(dist)}
__device__ __align__(16) float g_stats[DD+1];   // colsum[64], sumsq
__device__ __align__(16) float g_norm [DD+1];   // mu[64], inv
__device__ int   g_bsum[256];
__device__ int   g_barcnt = 0;
__device__ int   g_bargen = 0;
__device__ int   g_done   = 0;

// ---- software grid barrier (valid: all CSRB blocks resident) ----
__device__ __forceinline__ void grid_barrier() {
    __syncthreads();
    if (threadIdx.x == 0) {
        __threadfence();
        int gen = *(volatile int*)&g_bargen;
        if (atomicAdd(&g_barcnt, 1) == (int)gridDim.x - 1) {
            atomicExch(&g_barcnt, 0);
            __threadfence();
            atomicAdd(&g_bargen, 1);
        } else {
            while (*(volatile int*)&g_bargen == gen) { }
        }
        __threadfence();
    }
    __syncthreads();
}

// ---------------- fused: CSR build + input embedding + norm/stats init ----------------
__global__ void __launch_bounds__(256) k_csr_build(const int*   __restrict__ ei,
                                                   const float* __restrict__ pos,
                                                   const float* __restrict__ hin,
                                                   const float* __restrict__ Wemb,
                                                   const float* __restrict__ bemb) {
    __shared__ int s[256];
    int tid = threadIdx.x;
    int bid = blockIdx.x;
    int gt  = bid * 256 + tid;

    // init identity norm + zero stats
    if (gt < 64)  { g_norm[gt] = 0.f; g_stats[gt] = 0.f; }
    if (gt == 64) { g_norm[64] = 1.f; g_stats[64] = 0.f; g_done = 0; }

    // P0: zero counts
    if (gt < NN) g_cnt[gt] = 0;
    grid_barrier();

    // P1: count in-degree
    for (int e = gt; e < EE; e += CSRB * 256)
        atomicAdd(&g_cnt[ei[EE + e]], 1);
    grid_barrier();

    // P2: per-block scan
    {
        int c = (gt < NN) ? g_cnt[gt] : 0;
        s[tid] = c;
        __syncthreads();
        #pragma unroll
        for (int off = 1; off < 256; off <<= 1) {
            int t = 0;
            if (tid >= off) t = s[tid - off];
            __syncthreads();
            s[tid] += t;
            __syncthreads();
        }
        if (gt < NN) g_rowptr[gt] = s[tid] - c;
        if (tid == 255) g_bsum[bid] = s[255];
    }
    grid_barrier();

    // P3: scan block sums
    if (bid == 0) {
        int c = (tid < CSRB) ? g_bsum[tid] : 0;
        s[tid] = c;
        __syncthreads();
        #pragma unroll
        for (int off = 1; off < 256; off <<= 1) {
            int t = 0;
            if (tid >= off) t = s[tid - off];
            __syncthreads();
            s[tid] += t;
            __syncthreads();
        }
        if (tid < CSRB) g_bsum[tid] = s[tid] - c;
    }
    grid_barrier();

    // P4: globalize rowptr + cursors
    if (gt < NN) {
        int r = g_rowptr[gt] + g_bsum[bid];
        g_rowptr[gt] = r;
        g_cnt[gt] = r;
    }
    if (gt == 0) g_rowptr[NN] = EE;
    grid_barrier();

    // P5: fill CSR
    for (int e = gt; e < EE; e += CSRB * 256) {
        int sn = ei[e];
        int d  = ei[EE + e];
        int p  = atomicAdd(&g_cnt[d], 1);
        float dx = pos[2*d]   - pos[2*sn];
        float dy = pos[2*d+1] - pos[2*sn+1];
        g_csr[p] = make_int2(sn, __float_as_int(sqrtf(dx*dx + dy*dy)));
    }

    // P6: embedding (independent)
    int w0   = gt >> 5;
    int lane = tid & 31;
    int nw   = (CSRB * 256) >> 5;
    int c0   = lane * 2;
    for (int w = w0; w < NN; w += nw) {
        float v0 = hin[w*5+0], v1 = hin[w*5+1], v2 = hin[w*5+2],
              v3 = hin[w*5+3], v4 = hin[w*5+4];
        #pragma unroll
        for (int j = 0; j < 2; j++) {
            int c = c0 + j;
            float acc = bemb[c] + v0*Wemb[c] + v1*Wemb[64+c] + v2*Wemb[128+c]
                                + v3*Wemb[192+c] + v4*Wemb[256+c];
            g_hr[w*64+c] = fmaxf(acc, 0.f);
        }
    }
}

// ---------------- GEMM: [a|b] = pairnorm(hr) @ Wm_remap  (R1 tiling, norm fused) ----------------
__global__ void __launch_bounds__(256) k_gemm_ab(const float* __restrict__ Wm) {
    __shared__ float sXT[32][129];
    __shared__ float sW [32][128];
    int tid  = threadIdx.x;
    int base = blockIdx.x * 128;
    float inv = g_norm[64];
    int ng = tid & 15;     // nodes ng + 16*i
    int cg = tid >> 4;     // cols cg*8 .. +7  (0..127)
    float acc[8][8];
    #pragma unroll
    for (int i = 0; i < 8; i++)
        #pragma unroll
        for (int j = 0; j < 8; j++) acc[i][j] = 0.f;

    for (int kc = 0; kc < 64; kc += 32) {
        __syncthreads();
        // stage X^T with pairnorm applied
        #pragma unroll
        for (int it = 0; it < 4; it++) {
            int idx = tid + 256*it;
            int nl  = idx >> 3;
            int kq  = idx & 7;
            int n   = base + nl;
            float4 v = make_float4(0.f,0.f,0.f,0.f);
            if (n < NN) v = *(const float4*)&g_hr[n*64 + kc + kq*4];
            float4 mu = *(const float4*)&g_norm[kc + kq*4];
            v.x = (v.x - mu.x)*inv; v.y = (v.y - mu.y)*inv;
            v.z = (v.z - mu.z)*inv; v.w = (v.w - mu.w)*inv;
            sXT[kq*4+0][nl] = v.x;
            sXT[kq*4+1][nl] = v.y;
            sXT[kq*4+2][nl] = v.z;
            sXT[kq*4+3][nl] = v.w;
        }
        // stage W remap: col c<64 -> Wm[kc+kk][c] ; c>=64 -> Wm[64+kc+kk][c-64]
        #pragma unroll
        for (int it = 0; it < 16; it++) {
            int idx = tid + 256*it;
            int c   = idx & 127;
            int kk  = idx >> 7;          // 0..31
            int row = (c < 64) ? (kc + kk) : (64 + kc + kk);
            sW[kk][c] = Wm[row*64 + (c & 63)];
        }
        __syncthreads();
        #pragma unroll
        for (int kk = 0; kk < 32; kk++) {
            float xv[8];
            #pragma unroll
            for (int i = 0; i < 8; i++) xv[i] = sXT[kk][ng + 16*i];
            float4 wA = *(const float4*)&sW[kk][cg*8];
            float4 wB = *(const float4*)&sW[kk][cg*8 + 4];
            float wv[8] = {wA.x,wA.y,wA.z,wA.w,wB.x,wB.y,wB.z,wB.w};
            #pragma unroll
            for (int i = 0; i < 8; i++)
                #pragma unroll
                for (int j = 0; j < 8; j++)
                    acc[i][j] = fmaf(xv[i], wv[j], acc[i][j]);
        }
    }
    float* Out = (cg < 8) ? g_a : g_b;
    int c0     = (cg < 8) ? cg*8 : cg*8 - 64;
    #pragma unroll
    for (int i = 0; i < 8; i++) {
        int n = base + ng + 16*i;
        if (n < NN) {
            *(float4*)&Out[n*64 + c0]     = make_float4(acc[i][0],acc[i][1],acc[i][2],acc[i][3]);
            *(float4*)&Out[n*64 + c0 + 4] = make_float4(acc[i][4],acc[i][5],acc[i][6],acc[i][7]);
        }
    }
}

// ---------------- per-node edge gather (standalone, high occ, MLP=8) ----------------
__global__ void __launch_bounds__(256) k_gather(const float* __restrict__ Wm,
                                                const float* __restrict__ bm) {
    int gw   = (blockIdx.x*blockDim.x + threadIdx.x) >> 5;   // node id (grid exact)
    int lane = threadIdx.x & 31;
    int c0 = lane*2;
    float wdx = Wm[128*64 + c0], wdy = Wm[128*64 + c0 + 1];
    float2 av = *(const float2*)&g_a[gw*64 + c0];
    float pax = av.x + bm[c0];
    float pay = av.y + bm[c0+1];
    float ax = 0.f, ay = 0.f;
    int st = g_rowptr[gw], en = g_rowptr[gw+1];

    for (int eb = st; eb < en; eb += 8) {
        int mm = en - eb; if (mm > 8) mm = 8;
        int2 ed = make_int2(0, 0);
        if (lane < mm) ed = g_csr[eb + lane];
        float2 bv[8];
        float  dv[8];
        #pragma unroll
        for (int j = 0; j < 8; j++) {
            int sidx = __shfl_sync(0xffffffffu, ed.x, j);
            int dbit = __shfl_sync(0xffffffffu, ed.y, j);
            dv[j] = __int_as_float(dbit);
            if (j < mm) bv[j] = *(const float2*)&g_b[sidx*64 + c0];   // independent loads
        }
        #pragma unroll
        for (int j = 0; j < 8; j++) {
            if (j < mm) {
                ax += fmaxf(pax + bv[j].x + dv[j]*wdx, 0.f);
                ay += fmaxf(pay + bv[j].y + dv[j]*wdy, 0.f);
            }
        }
    }
    *(float2*)&g_aggr[gw*64 + c0] = make_float2(ax, ay);
}

// ---------------- update GEMM (R1 tiling): h2 = relu([norm(h)|aggr] @ Wu + bu) + stats + finalize ----------------
__global__ void __launch_bounds__(256) k_gemm_upd(const float* __restrict__ Wu,
                                                  const float* __restrict__ bu) {
    __shared__ float sXT[32][129];
    __shared__ float sW [32][68];
    int tid  = threadIdx.x;
    int base = blockIdx.x * 128;
    float inv = g_norm[64];
    int ng = tid & 15;
    int cg = tid >> 4;          // cols cg*4 .. +3 (0..63)
    float acc[8][4];
    #pragma unroll
    for (int i = 0; i < 8; i++)
        #pragma unroll
        for (int j = 0; j < 4; j++) acc[i][j] = 0.f;

    for (int kc = 0; kc < 128; kc += 32) {
        __syncthreads();
        const bool fromH = (kc < 64);
        const float* Xsrc = fromH ? g_hr : g_aggr;
        int koff = kc & 63;
        #pragma unroll
        for (int it = 0; it < 4; it++) {
            int idx = tid + 256*it;
            int nl  = idx >> 3;
            int kq  = idx & 7;
            int n   = base + nl;
            float4 v = make_float4(0.f,0.f,0.f,0.f);
            if (n < NN) v = *(const float4*)&Xsrc[n*64 + koff + kq*4];
            if (fromH) {
                float4 mu = *(const float4*)&g_norm[koff + kq*4];
                v.x = (v.x - mu.x)*inv; v.y = (v.y - mu.y)*inv;
                v.z = (v.z - mu.z)*inv; v.w = (v.w - mu.w)*inv;
            }
            sXT[kq*4+0][nl] = v.x;
            sXT[kq*4+1][nl] = v.y;
            sXT[kq*4+2][nl] = v.z;
            sXT[kq*4+3][nl] = v.w;
        }
        #pragma unroll
        for (int it = 0; it < 8; it++) {
            int idx = tid + 256*it;     // 2048 floats
            int c   = idx & 63;
            int kk  = idx >> 6;
            sW[kk][c] = Wu[(kc + kk)*64 + c];
        }
        __syncthreads();
        #pragma unroll
        for (int kk = 0; kk < 32; kk++) {
            float xv[8];
            #pragma unroll
            for (int i = 0; i < 8; i++) xv[i] = sXT[kk][ng + 16*i];
            float4 w = *(const float4*)&sW[kk][cg*4];
            float wv[4] = {w.x, w.y, w.z, w.w};
            #pragma unroll
            for (int i = 0; i < 8; i++)
                #pragma unroll
                for (int j = 0; j < 4; j++)
                    acc[i][j] = fmaf(xv[i], wv[j], acc[i][j]);
        }
    }
    int c0 = cg*4;
    float4 bb = *(const float4*)&bu[c0];
    float bvv[4] = {bb.x, bb.y, bb.z, bb.w};
    float ls[4] = {0.f,0.f,0.f,0.f};
    float lss = 0.f;
    #pragma unroll
    for (int i = 0; i < 8; i++) {
        int n = base + ng + 16*i;
        if (n < NN) {
            float o[4];
            #pragma unroll
            for (int j = 0; j < 4; j++) {
                o[j] = fmaxf(acc[i][j] + bvv[j], 0.f);
                ls[j] += o[j];
                lss   += o[j]*o[j];
            }
            *(float4*)&g_hr[n*64 + c0] = make_float4(o[0],o[1],o[2],o[3]);
        }
    }
    // width-16 segment reduce (lanes sharing this cg)
    #pragma unroll
    for (int off = 8; off >= 1; off >>= 1) {
        #pragma unroll
        for (int j = 0; j < 4; j++)
            ls[j] += __shfl_down_sync(0xffffffffu, ls[j], off, 16);
        lss += __shfl_down_sync(0xffffffffu, lss, off, 16);
    }
    if ((tid & 15) == 0) {
        #pragma unroll
        for (int j = 0; j < 4; j++) atomicAdd(&g_stats[c0 + j], ls[j]);
        atomicAdd(&g_stats[64], lss);
    }

    // ---- last block finalizes g_norm for next consumer, re-arms stats ----
    __shared__ int isLast;
    __threadfence();
    __syncthreads();
    if (tid == 0)
        isLast = (atomicAdd(&g_done, 1) == (int)gridDim.x - 1) ? 1 : 0;
    __syncthreads();
    if (isLast) {
        __shared__ float spart[2];
        if (tid < 64) {
            float mu = g_stats[tid] * (1.0f/NN);
            g_norm[tid] = mu;
            float m2 = mu*mu;
            #pragma unroll
            for (int off = 16; off > 0; off >>= 1)
                m2 += __shfl_down_sync(0xffffffffu, m2, off);
            if ((tid & 31) == 0) spart[tid >> 5] = m2;
        }
        __syncthreads();
        if (tid == 0) {
            float musq = spart[0] + spart[1];
            g_norm[64] = 1.0f / sqrtf(1e-5f + g_stats[64]*(1.0f/NN) - musq);
            g_done = 0;
        }
        __syncthreads();
        if (tid < 65) g_stats[tid] = 0.f;   // re-arm for next layer
    }
}

// ---------------- per-graph max pool (raw h + lazy norm, monotone) + tiny MLP ----------------
__global__ void k_pool(const float* __restrict__ W1, const float* __restrict__ b1,
                       const float* __restrict__ W2, const float* __restrict__ b2,
                       float* __restrict__ out) {
    __shared__ float red[4][64];
    __shared__ float hg[64];
    __shared__ float z[64];
    int g   = blockIdx.x;
    int tid = threadIdx.x;
    int c     = tid & 63;
    int chunk = tid >> 6;
    float m = -3.4e38f;
    int nbeg = g*NPG + chunk*(NPG/4);
    for (int i = 0; i < NPG/4; i++)
        m = fmaxf(m, g_hr[(nbeg + i)*64 + c]);
    red[chunk][c] = m;
    __syncthreads();
    if (tid < 64) {
        float mr = fmaxf(fmaxf(red[0][tid], red[1][tid]),
                         fmaxf(red[2][tid], red[3][tid]));
        hg[tid] = (mr - g_norm[tid]) * g_norm[64];   // pairnorm monotone per column
    }
    __syncthreads();
    if (tid < 64) {
        float acc = b1[tid];
        for (int k = 0; k < 64; k++) acc = fmaf(hg[k], W1[k*64 + tid], acc);
        z[tid] = fmaxf(acc, 0.f);
    }
    __syncthreads();
    if (tid < 2) {
        float acc = b2[tid];
        for (int k = 0; k < 64; k++) acc = fmaf(z[k], W2[k*2 + tid], acc);
        out[g*2 + tid] = acc;
    }
}

// ---------------- launch ----------------
extern "C" void kernel_launch(void* const* d_in, const int* in_sizes, int n_in,
                              void* d_out, int out_size) {
    const float* h_in = (const float*)d_in[0];
    const float* pos  = (const float*)d_in[1];
    const int*   ei   = (const int*)  d_in[2];
    // d_in[3] = batch — structure fixed (contiguous 1000-node graphs), unused
    const float* Wemb = (const float*)d_in[4];
    const float* bemb = (const float*)d_in[5];
    const float* msgW = (const float*)d_in[6];
    const float* msgb = (const float*)d_in[7];
    const float* updW = (const float*)d_in[8];
    const float* updb = (const float*)d_in[9];
    const float* W1   = (const float*)d_in[10];
    const float* b1   = (const float*)d_in[11];
    const float* W2   = (const float*)d_in[12];
    const float* b2   = (const float*)d_in[13];
    float* out = (float*)d_out;

    k_csr_build<<<CSRB, 256>>>(ei, pos, h_in, Wemb, bemb);

    for (int l = 0; l < 2; l++) {
        const float* Wm = msgW + l*129*64;
        const float* bm = msgb + l*64;
        const float* Wu = updW + l*128*64;
        const float* bu = updb + l*64;
        k_gemm_ab <<<391, 256>>>(Wm);
        k_gather  <<<6250, 256>>>(Wm, bm);
        k_gemm_upd<<<391, 256>>>(Wu, bu);
    }

    k_pool<<<50, 256>>>(W1, b1, W2, b2, out);
}